// round 1
// baseline (speedup 1.0000x reference)
#include <cuda_runtime.h>
#include <math.h>

#define THREADS 512
#define TR 128   // rows per block

// Shared memory layout (floats):
//  sW1  : 18*128   = 2304
//  sW2  : 128*128  = 16384   (cols 0..53 = W2a, 54..125 = W2b, 126..127 = 0)
//  sU   : 128*36   = 4608
//  sH   : 128*128  = 16384   (h after layer1; overwritten with GEMM result)
//  sB1  : 128
//  sB2a : 54
//  sB2b : 72
//  sR   : 10 (reg1[0..5], reg2[0..3])
#define SMEM_FLOATS (2304 + 16384 + 4608 + 16384 + 128 + 54 + 72 + 10)

__global__ __launch_bounds__(THREADS, 1)
void mixmodel_kernel(const float* __restrict__ u,
                     const float* __restrict__ reg1,
                     const float* __restrict__ reg2,
                     const float* __restrict__ W1,
                     const float* __restrict__ b1,
                     const float* __restrict__ W2a,
                     const float* __restrict__ b2a,
                     const float* __restrict__ W2b,
                     const float* __restrict__ b2b,
                     float* __restrict__ out,
                     int N)
{
    extern __shared__ float sm[];
    float* sW1  = sm;                 // 2304
    float* sW2  = sW1 + 18 * 128;     // 16384
    float* sU   = sW2 + 128 * 128;    // 4608
    float* sH   = sU + 128 * 36;      // 16384
    float* sB1  = sH + 128 * 128;     // 128
    float* sB2a = sB1 + 128;          // 54
    float* sB2b = sB2a + 54;          // 72
    float* sR   = sB2b + 72;          // 10

    const int tid = threadIdx.x;
    const int rowbase = blockIdx.x * TR;

    // ---- load weights / biases / reg coefficients into SMEM ----
    for (int i = tid; i < 18 * 128; i += THREADS) sW1[i] = W1[i];
    for (int i = tid; i < 128 * 128; i += THREADS) {
        int k = i >> 7;
        int c = i & 127;
        float v = 0.0f;
        if (c < 54)       v = W2a[k * 54 + c];
        else if (c < 126) v = W2b[k * 72 + (c - 54)];
        sW2[i] = v;
    }
    if (tid < 128) sB1[tid]  = b1[tid];
    if (tid < 54)  sB2a[tid] = b2a[tid];
    if (tid < 72)  sB2b[tid] = b2b[tid];
    if (tid < 6)   sR[tid]     = reg1[tid];
    if (tid < 4)   sR[6 + tid] = reg2[tid];

    // ---- load u tile (coalesced), zero-fill out-of-range rows ----
    {
        const int total = TR * 36;
        const float* gsrc = u + (size_t)rowbase * 36;
        long long avail = ((long long)N - rowbase) * 36;
        if (avail < 0) avail = 0;
        if (avail > total) avail = total;
        for (int i = tid; i < total; i += THREADS)
            sU[i] = (i < (int)avail) ? gsrc[i] : 0.0f;
    }
    __syncthreads();

    const int warp = tid >> 5;       // 0..15 -> 8 rows each
    const int lane = tid & 31;       // -> 4 cols each
    const int r0 = warp * 8;
    const int c0 = lane * 4;

    float acc[8][4];

    // ---- layer 1: h = tanh(u_even @ W1 + b1), tile 8 rows x 4 cols / thread
    #pragma unroll
    for (int r = 0; r < 8; r++)
        #pragma unroll
        for (int c = 0; c < 4; c++) acc[r][c] = 0.0f;

    #pragma unroll
    for (int j = 0; j < 18; j++) {
        float4 w = *(const float4*)&sW1[j * 128 + c0];
        #pragma unroll
        for (int r = 0; r < 8; r++) {
            float uv = sU[(r0 + r) * 36 + 2 * j];   // broadcast within warp
            acc[r][0] = fmaf(uv, w.x, acc[r][0]);
            acc[r][1] = fmaf(uv, w.y, acc[r][1]);
            acc[r][2] = fmaf(uv, w.z, acc[r][2]);
            acc[r][3] = fmaf(uv, w.w, acc[r][3]);
        }
    }
    {
        float4 bb = *(const float4*)&sB1[c0];
        #pragma unroll
        for (int r = 0; r < 8; r++) {
            float4 hv;
            hv.x = tanhf(acc[r][0] + bb.x);
            hv.y = tanhf(acc[r][1] + bb.y);
            hv.z = tanhf(acc[r][2] + bb.z);
            hv.w = tanhf(acc[r][3] + bb.w);
            *(float4*)&sH[(r0 + r) * 128 + c0] = hv;
        }
    }
    __syncthreads();

    // ---- layer 2: out = h @ W2 (128 x 126), 8x4 register tile, k-unroll 4
    #pragma unroll
    for (int r = 0; r < 8; r++)
        #pragma unroll
        for (int c = 0; c < 4; c++) acc[r][c] = 0.0f;

    for (int k = 0; k < 128; k += 4) {
        float4 h4[8];
        #pragma unroll
        for (int r = 0; r < 8; r++)
            h4[r] = *(const float4*)&sH[(r0 + r) * 128 + k];  // broadcast

        #pragma unroll
        for (int kk = 0; kk < 4; kk++) {
            float4 w = *(const float4*)&sW2[(k + kk) * 128 + c0];
            #pragma unroll
            for (int r = 0; r < 8; r++) {
                float hv = (kk == 0) ? h4[r].x : (kk == 1) ? h4[r].y
                          : (kk == 2) ? h4[r].z : h4[r].w;
                acc[r][0] = fmaf(hv, w.x, acc[r][0]);
                acc[r][1] = fmaf(hv, w.y, acc[r][1]);
                acc[r][2] = fmaf(hv, w.z, acc[r][2]);
                acc[r][3] = fmaf(hv, w.w, acc[r][3]);
            }
        }
    }
    __syncthreads();   // all reads of sH (h values) complete

    // write GEMM result back into sH (reuse)
    #pragma unroll
    for (int r = 0; r < 8; r++)
        *(float4*)&sH[(r0 + r) * 128 + c0] =
            make_float4(acc[r][0], acc[r][1], acc[r][2], acc[r][3]);
    __syncthreads();

    // ---- epilogue: biases + regression features + uA/uB/uC combine ----
    const float r1_0 = sR[0], r1_1 = sR[1], r1_2 = sR[2];
    const float r1_3 = sR[3], r1_4 = sR[4], r1_5 = sR[5];
    const float r2_0 = sR[6], r2_1 = sR[7], r2_2 = sR[8], r2_3 = sR[9];

    for (int idx = tid; idx < TR * 18; idx += THREADS) {
        int row = idx / 18;
        int i   = idx - row * 18;
        int grow = rowbase + row;
        if (grow >= N) continue;

        const float* ur = &sU[row * 36];
        int i2 = 2 * i;
        float uE  = ur[i2];                 // u[2i]
        float uB  = ur[i2 + 1];             // u[2i+1]
        float uA  = ur[(i2 + 35) % 36];     // u[2i-1]
        float uC  = ur[(i2 + 3) % 36];      // u[2i+3]
        float um2 = ur[(i2 + 34) % 36];     // u[2i-2]
        float up2 = ur[(i2 + 2) % 36];      // u[2i+2]

        // regression parts
        float e = r1_0 + r1_1 * uE + r1_2 * uB
                + r1_3 * (um2 * uA) + r1_4 * (uA * up2) + r1_5 * (uE * uB);
        float o = r2_0 + r2_1 * uB + r2_2 * (uA * uE) + r2_3 * (uE * up2);

        const float* hr = &sH[row * 128];
        float a0 = hr[3 * i]     + sB2a[3 * i];
        float a1 = hr[3 * i + 1] + sB2a[3 * i + 1];
        float a2 = hr[3 * i + 2] + sB2a[3 * i + 2];
        float d0 = hr[54 + 4 * i]     + sB2b[4 * i];
        float d1 = hr[54 + 4 * i + 1] + sB2b[4 * i + 1];
        float d2 = hr[54 + 4 * i + 2] + sB2b[4 * i + 2];
        float d3 = hr[54 + 4 * i + 3] + sB2b[4 * i + 3];

        float oE = a0 + a1 * uA + a2 * uB + e;
        float oO = d0 + d1 * uA + d2 * uB + d3 * uC + o;

        *(float2*)&out[(size_t)grow * 36 + i2] = make_float2(oE, oO);
    }
}

extern "C" void kernel_launch(void* const* d_in, const int* in_sizes, int n_in,
                              void* d_out, int out_size)
{
    // inputs: 0=t(scalar,unused) 1=u 2=reg1 3=reg2 4=W1 5=b1 6=W2a 7=b2a 8=W2b 9=b2b
    const float* u    = (const float*)d_in[1];
    const float* reg1 = (const float*)d_in[2];
    const float* reg2 = (const float*)d_in[3];
    const float* W1   = (const float*)d_in[4];
    const float* b1   = (const float*)d_in[5];
    const float* W2a  = (const float*)d_in[6];
    const float* b2a  = (const float*)d_in[7];
    const float* W2b  = (const float*)d_in[8];
    const float* b2b  = (const float*)d_in[9];
    float* out = (float*)d_out;

    int N = in_sizes[1] / 36;
    int smem_bytes = SMEM_FLOATS * (int)sizeof(float);

    cudaFuncSetAttribute(mixmodel_kernel,
                         cudaFuncAttributeMaxDynamicSharedMemorySize, smem_bytes);

    int blocks = (N + TR - 1) / TR;
    mixmodel_kernel<<<blocks, THREADS, smem_bytes>>>(
        u, reg1, reg2, W1, b1, W2a, b2a, W2b, b2b, out, N);
}

// round 3
// speedup vs baseline: 1.2895x; 1.2895x over previous
#include <cuda_runtime.h>
#include <cstdint>
#include <math.h>

#define TPB 512
#define TRR 128
#define LDH 132   // smem row stride (floats) for W2 / H / W1
#define LDA 28    // smem row stride for A1 (u_even, K padded to 24)

// ---- shared memory layout (float offsets) ----
#define OFF_W2   0                    // 128*132 = 16896  [k][n]
#define OFF_H    (OFF_W2 + 128*LDH)   // 128*132 = 16896  [m][k] h (tf32 bits), then D (f32)
#define OFF_W1   (OFF_H + 128*LDH)    // 24*132  = 3168   [k][n]
#define OFF_A1   (OFF_W1 + 24*LDH)    // 128*28  = 3584   [m][k] u_even (tf32 bits)
#define OFF_U    (OFF_A1 + 128*LDA)   // 128*36  = 4608
#define OFF_B1   (OFF_U + 128*36)     // 128
#define OFF_B2A  (OFF_B1 + 128)       // 54 -> pad 56
#define OFF_B2B  (OFF_B2A + 56)       // 72
#define OFF_R    (OFF_B2B + 72)       // 10
#define SMEM_FLOATS (OFF_R + 12)

__device__ __forceinline__ uint32_t f2tf32(float x) {
    uint32_t r;
    asm("cvt.rna.tf32.f32 %0, %1;" : "=r"(r) : "f"(x));
    return r;
}

__device__ __forceinline__ void mma_tf32(float c[4],
                                         uint32_t a0, uint32_t a1, uint32_t a2, uint32_t a3,
                                         uint32_t b0, uint32_t b1) {
    asm volatile(
        "mma.sync.aligned.m16n8k8.row.col.f32.tf32.tf32.f32 "
        "{%0,%1,%2,%3}, {%4,%5,%6,%7}, {%8,%9}, {%0,%1,%2,%3};"
        : "+f"(c[0]), "+f"(c[1]), "+f"(c[2]), "+f"(c[3])
        : "r"(a0), "r"(a1), "r"(a2), "r"(a3), "r"(b0), "r"(b1));
}

__global__ __launch_bounds__(TPB, 1)
void mix_mma_kernel(const float* __restrict__ u,
                    const float* __restrict__ reg1,
                    const float* __restrict__ reg2,
                    const float* __restrict__ W1,
                    const float* __restrict__ b1,
                    const float* __restrict__ W2a,
                    const float* __restrict__ b2a,
                    const float* __restrict__ W2b,
                    const float* __restrict__ b2b,
                    float* __restrict__ out,
                    int N)
{
    extern __shared__ float sm[];
    uint32_t* smu = (uint32_t*)sm;

    const int tid  = threadIdx.x;
    const int wid  = tid >> 5;
    const int lane = tid & 31;
    const int gid  = lane >> 2;   // 0..7
    const int t4   = lane & 3;    // 0..3
    const int wm   = (wid & 3) * 32;   // warp row base
    const int wn   = (wid >> 2) * 32;  // warp col base
    const int rowbase = blockIdx.x * TRR;

    // ---- stage weights (tf32-rounded), biases, reg coeffs ----
    for (int i = tid; i < 128 * 128; i += TPB) {
        int k = i >> 7, n = i & 127;
        float v = 0.0f;
        if (n < 54)       v = W2a[k * 54 + n];
        else if (n < 126) v = W2b[k * 72 + (n - 54)];
        smu[OFF_W2 + k * LDH + n] = f2tf32(v);
    }
    for (int i = tid; i < 24 * 128; i += TPB) {
        int k = i >> 7, n = i & 127;
        float v = (k < 18) ? W1[k * 128 + n] : 0.0f;
        smu[OFF_W1 + k * LDH + n] = f2tf32(v);
    }
    if (tid < 128) sm[OFF_B1 + tid]  = b1[tid];
    if (tid < 54)  sm[OFF_B2A + tid] = b2a[tid];
    if (tid < 72)  sm[OFF_B2B + tid] = b2b[tid];
    if (tid < 6)   sm[OFF_R + tid]     = reg1[tid];
    if (tid < 4)   sm[OFF_R + 6 + tid] = reg2[tid];

    // ---- load u tile (coalesced), zero-fill OOR ----
    {
        const int total = TRR * 36;
        const float* gsrc = u + (size_t)rowbase * 36;
        long long avail = ((long long)N - rowbase) * 36;
        if (avail < 0) avail = 0;
        if (avail > total) avail = total;
        for (int i = tid; i < total; i += TPB)
            sm[OFF_U + i] = (i < (int)avail) ? gsrc[i] : 0.0f;
    }
    __syncthreads();

    // ---- build A1 = tf32(u_even) [128][24] ----
    for (int i = tid; i < TRR * 24; i += TPB) {
        int m = i / 24, k = i - m * 24;
        float v = (k < 18) ? sm[OFF_U + m * 36 + 2 * k] : 0.0f;
        smu[OFF_A1 + m * LDA + k] = f2tf32(v);
    }
    __syncthreads();

    float acc[2][4][4];   // [mt][nt][frag]

    // ================= layer 1: pre-h = A1 @ W1 =================
    #pragma unroll
    for (int mt = 0; mt < 2; mt++)
        #pragma unroll
        for (int nt = 0; nt < 4; nt++)
            #pragma unroll
            for (int f = 0; f < 4; f++) acc[mt][nt][f] = 0.0f;

    #pragma unroll
    for (int kc = 0; kc < 3; kc++) {
        const int kb = kc * 8;
        uint32_t A[2][4];
        #pragma unroll
        for (int mt = 0; mt < 2; mt++) {
            int r = wm + mt * 16;
            A[mt][0] = smu[OFF_A1 + (r + gid)     * LDA + kb + t4];
            A[mt][1] = smu[OFF_A1 + (r + gid + 8) * LDA + kb + t4];
            A[mt][2] = smu[OFF_A1 + (r + gid)     * LDA + kb + t4 + 4];
            A[mt][3] = smu[OFF_A1 + (r + gid + 8) * LDA + kb + t4 + 4];
        }
        #pragma unroll
        for (int nt = 0; nt < 4; nt++) {
            int c = wn + nt * 8;
            uint32_t b0 = smu[OFF_W1 + (kb + t4)     * LDH + c + gid];
            uint32_t b1f = smu[OFF_W1 + (kb + t4 + 4) * LDH + c + gid];
            #pragma unroll
            for (int mt = 0; mt < 2; mt++)
                mma_tf32(acc[mt][nt], A[mt][0], A[mt][1], A[mt][2], A[mt][3], b0, b1f);
        }
    }

    // bias + tanh + tf32-round, stage h to sH
    #pragma unroll
    for (int mt = 0; mt < 2; mt++) {
        #pragma unroll
        for (int nt = 0; nt < 4; nt++) {
            int c = wn + nt * 8 + 2 * t4;
            float bb0 = sm[OFF_B1 + c], bb1 = sm[OFF_B1 + c + 1];
            int r0 = wm + mt * 16 + gid;
            uint32_t h00 = f2tf32(tanhf(acc[mt][nt][0] + bb0));
            uint32_t h01 = f2tf32(tanhf(acc[mt][nt][1] + bb1));
            uint32_t h10 = f2tf32(tanhf(acc[mt][nt][2] + bb0));
            uint32_t h11 = f2tf32(tanhf(acc[mt][nt][3] + bb1));
            *(uint2*)&smu[OFF_H + r0 * LDH + c]       = make_uint2(h00, h01);
            *(uint2*)&smu[OFF_H + (r0 + 8) * LDH + c] = make_uint2(h10, h11);
        }
    }
    __syncthreads();

    // ================= layer 2: D = H @ W2 =================
    #pragma unroll
    for (int mt = 0; mt < 2; mt++)
        #pragma unroll
        for (int nt = 0; nt < 4; nt++)
            #pragma unroll
            for (int f = 0; f < 4; f++) acc[mt][nt][f] = 0.0f;

    #pragma unroll
    for (int kc = 0; kc < 16; kc++) {
        const int kb = kc * 8;
        uint32_t A[2][4];
        #pragma unroll
        for (int mt = 0; mt < 2; mt++) {
            int r = wm + mt * 16;
            A[mt][0] = smu[OFF_H + (r + gid)     * LDH + kb + t4];
            A[mt][1] = smu[OFF_H + (r + gid + 8) * LDH + kb + t4];
            A[mt][2] = smu[OFF_H + (r + gid)     * LDH + kb + t4 + 4];
            A[mt][3] = smu[OFF_H + (r + gid + 8) * LDH + kb + t4 + 4];
        }
        #pragma unroll
        for (int nt = 0; nt < 4; nt++) {
            int c = wn + nt * 8;
            uint32_t b0 = smu[OFF_W2 + (kb + t4)     * LDH + c + gid];
            uint32_t b1f = smu[OFF_W2 + (kb + t4 + 4) * LDH + c + gid];
            #pragma unroll
            for (int mt = 0; mt < 2; mt++)
                mma_tf32(acc[mt][nt], A[mt][0], A[mt][1], A[mt][2], A[mt][3], b0, b1f);
        }
    }
    __syncthreads();   // all h reads complete before overwriting sH with D

    #pragma unroll
    for (int mt = 0; mt < 2; mt++) {
        #pragma unroll
        for (int nt = 0; nt < 4; nt++) {
            int c = wn + nt * 8 + 2 * t4;
            int r0 = wm + mt * 16 + gid;
            *(float2*)&sm[OFF_H + r0 * LDH + c]       = make_float2(acc[mt][nt][0], acc[mt][nt][1]);
            *(float2*)&sm[OFF_H + (r0 + 8) * LDH + c] = make_float2(acc[mt][nt][2], acc[mt][nt][3]);
        }
    }
    __syncthreads();

    // ================= fused epilogue =================
    const float r10 = sm[OFF_R + 0], r11 = sm[OFF_R + 1], r12 = sm[OFF_R + 2];
    const float r13 = sm[OFF_R + 3], r14 = sm[OFF_R + 4], r15 = sm[OFF_R + 5];
    const float r20 = sm[OFF_R + 6], r21 = sm[OFF_R + 7], r22 = sm[OFF_R + 8], r23 = sm[OFF_R + 9];

    for (int idx = tid; idx < TRR * 18; idx += TPB) {
        int row = idx / 18;
        int i   = idx - row * 18;
        int grow = rowbase + row;
        if (grow >= N) continue;

        const float* ur = &sm[OFF_U + row * 36];
        int i2 = 2 * i;
        float uE  = ur[i2];
        float uB  = ur[i2 + 1];
        float uA  = ur[(i2 + 35) % 36];
        float uC  = ur[(i2 + 3) % 36];
        float um2 = ur[(i2 + 34) % 36];
        float up2 = ur[(i2 + 2) % 36];

        float e = r10 + r11 * uE + r12 * uB
                + r13 * (um2 * uA) + r14 * (uA * up2) + r15 * (uE * uB);
        float o = r20 + r21 * uB + r22 * (uA * uE) + r23 * (uE * up2);

        const float* hr = &sm[OFF_H + row * LDH];
        float a0 = hr[3 * i]     + sm[OFF_B2A + 3 * i];
        float a1 = hr[3 * i + 1] + sm[OFF_B2A + 3 * i + 1];
        float a2 = hr[3 * i + 2] + sm[OFF_B2A + 3 * i + 2];
        float d0 = hr[54 + 4 * i]     + sm[OFF_B2B + 4 * i];
        float d1 = hr[54 + 4 * i + 1] + sm[OFF_B2B + 4 * i + 1];
        float d2 = hr[54 + 4 * i + 2] + sm[OFF_B2B + 4 * i + 2];
        float d3 = hr[54 + 4 * i + 3] + sm[OFF_B2B + 4 * i + 3];

        float oE = a0 + a1 * uA + a2 * uB + e;
        float oO = d0 + d1 * uA + d2 * uB + d3 * uC + o;
        *(float2*)&out[(size_t)grow * 36 + i2] = make_float2(oE, oO);
    }
}

extern "C" void kernel_launch(void* const* d_in, const int* in_sizes, int n_in,
                              void* d_out, int out_size)
{
    // inputs: 0=t 1=u 2=reg1 3=reg2 4=W1 5=b1 6=W2a 7=b2a 8=W2b 9=b2b
    const float* u    = (const float*)d_in[1];
    const float* reg1 = (const float*)d_in[2];
    const float* reg2 = (const float*)d_in[3];
    const float* W1   = (const float*)d_in[4];
    const float* b1   = (const float*)d_in[5];
    const float* W2a  = (const float*)d_in[6];
    const float* b2a  = (const float*)d_in[7];
    const float* W2b  = (const float*)d_in[8];
    const float* b2b  = (const float*)d_in[9];
    float* out = (float*)d_out;

    int N = in_sizes[1] / 36;
    int blocks = (N + TRR - 1) / TRR;
    int smem_bytes = SMEM_FLOATS * (int)sizeof(float);

    cudaFuncSetAttribute(mix_mma_kernel,
                         cudaFuncAttributeMaxDynamicSharedMemorySize, smem_bytes);
    mix_mma_kernel<<<blocks, TPB, smem_bytes>>>(
        u, reg1, reg2, W1, b1, W2a, b2a, W2b, b2b, out, N);
}

// round 4
// speedup vs baseline: 3.5838x; 2.7791x over previous
#include <cuda_runtime.h>
#include <cstdint>
#include <math.h>

#define TPB 512
#define TRR 128
#define LDH 132   // row stride (floats) for W2 / H / W1 — conflict-free frag loads

// ---- shared memory layout (float offsets) ----
#define OFF_W2   0                     // 128*132 [k][n] tf32 bits
#define OFF_H    (OFF_W2 + 128*LDH)    // 128*132 [m][k] h (f32 bits), then D (f32)
#define OFF_W1   (OFF_H + 128*LDH)     // 24*132  [k][n] tf32 bits (k>=18 zero)
#define OFF_U0   (OFF_W1 + 24*LDH)     // 128*36 raw u, buffer 0
#define OFF_U1   (OFF_U0 + TRR*36)     // buffer 1
#define OFF_B1   (OFF_U1 + TRR*36)     // 128
#define OFF_B2A  (OFF_B1 + 128)        // 54 -> pad 56
#define OFF_B2B  (OFF_B2A + 56)        // 72
#define OFF_R    (OFF_B2B + 72)        // 10
#define SMEM_FLOATS (OFF_R + 12)

__device__ __forceinline__ uint32_t f2tf32(float x) {
    uint32_t r;
    asm("cvt.rna.tf32.f32 %0, %1;" : "=r"(r) : "f"(x));
    return r;
}
__device__ __forceinline__ float tanh_fast(float x) {
    float y;
    asm("tanh.approx.f32 %0, %1;" : "=f"(y) : "f"(x));
    return y;
}
__device__ __forceinline__ void mma_tf32(float c[4],
                                         uint32_t a0, uint32_t a1, uint32_t a2, uint32_t a3,
                                         uint32_t b0, uint32_t b1) {
    asm volatile(
        "mma.sync.aligned.m16n8k8.row.col.f32.tf32.tf32.f32 "
        "{%0,%1,%2,%3}, {%4,%5,%6,%7}, {%8,%9}, {%0,%1,%2,%3};"
        : "+f"(c[0]), "+f"(c[1]), "+f"(c[2]), "+f"(c[3])
        : "r"(a0), "r"(a1), "r"(a2), "r"(a3), "r"(b0), "r"(b1));
}
__device__ __forceinline__ void cp16(uint32_t dst, const void* src) {
    asm volatile("cp.async.cg.shared.global [%0], [%1], 16;" :: "r"(dst), "l"(src));
}
#define CP_COMMIT() asm volatile("cp.async.commit_group;" ::: "memory")
#define CP_WAIT(n)  asm volatile("cp.async.wait_group %0;" :: "n"(n) : "memory")

__global__ __launch_bounds__(TPB, 1)
void mix_mma_pers(const float* __restrict__ u,
                  const float* __restrict__ reg1,
                  const float* __restrict__ reg2,
                  const float* __restrict__ W1,
                  const float* __restrict__ b1,
                  const float* __restrict__ W2a,
                  const float* __restrict__ b2a,
                  const float* __restrict__ W2b,
                  const float* __restrict__ b2b,
                  float* __restrict__ out,
                  int N, int ntiles)
{
    extern __shared__ float sm[];
    uint32_t* smu = (uint32_t*)sm;
    const uint32_t smem_base = (uint32_t)__cvta_generic_to_shared(sm);

    const int tid  = threadIdx.x;
    const int wid  = tid >> 5;
    const int lane = tid & 31;
    const int gid  = lane >> 2;       // 0..7
    const int t4   = lane & 3;        // 0..3
    const int wm   = (wid & 3) * 32;  // warp row base
    const int wn   = (wid >> 2) * 32; // warp col base

    // ---- prologue: prefetch first u tile into buffer 0 ----
    const int tile0 = blockIdx.x;
    {
        int rows = min(TRR, N - tile0 * TRR);
        int n16  = rows * 9;   // 36 floats = 9 x 16B per row
        const char* gsrc = (const char*)(u + (size_t)tile0 * TRR * 36);
        uint32_t dst = smem_base + OFF_U0 * 4;
        for (int i = tid; i < n16; i += TPB) cp16(dst + i * 16, gsrc + i * 16);
    }
    CP_COMMIT();

    // ---- stage weights once (tf32 RNA-rounded), biases, reg coeffs ----
    for (int i = tid; i < 128 * 128; i += TPB) {
        int k = i >> 7, n = i & 127;
        float v = 0.0f;
        if (n < 54)       v = W2a[k * 54 + n];
        else if (n < 126) v = W2b[k * 72 + (n - 54)];
        smu[OFF_W2 + k * LDH + n] = f2tf32(v);
    }
    for (int i = tid; i < 24 * 128; i += TPB) {
        int k = i >> 7, n = i & 127;
        float v = (k < 18) ? W1[k * 128 + n] : 0.0f;
        smu[OFF_W1 + k * LDH + n] = f2tf32(v);
    }
    if (tid < 128) sm[OFF_B1 + tid]  = b1[tid];
    if (tid < 54)  sm[OFF_B2A + tid] = b2a[tid];
    if (tid < 72)  sm[OFF_B2B + tid] = b2b[tid];
    if (tid < 6)   sm[OFF_R + tid]     = reg1[tid];
    if (tid < 4)   sm[OFF_R + 6 + tid] = reg2[tid];
    __syncthreads();

    const float r10 = sm[OFF_R + 0], r11 = sm[OFF_R + 1], r12 = sm[OFF_R + 2];
    const float r13 = sm[OFF_R + 3], r14 = sm[OFF_R + 4], r15 = sm[OFF_R + 5];
    const float r20 = sm[OFF_R + 6], r21 = sm[OFF_R + 7], r22 = sm[OFF_R + 8], r23 = sm[OFF_R + 9];

    const int erow = tid >> 2;     // epilogue: 4 threads per row
    const int esub = tid & 3;

    float acc[2][4][4];

    int it = 0;
    for (int tile = tile0; tile < ntiles; tile += gridDim.x, ++it) {
        const int b = it & 1;
        const float* sU = sm + (b ? OFF_U1 : OFF_U0);
        const uint32_t* uU = (const uint32_t*)sU;

        __syncthreads();   // prior epilogue done -> other buffer reusable
        int ntile = tile + gridDim.x;
        if (ntile < ntiles) {
            int rows = min(TRR, N - ntile * TRR);
            int n16  = rows * 9;
            const char* gsrc = (const char*)(u + (size_t)ntile * TRR * 36);
            uint32_t dst = smem_base + (b ? OFF_U0 : OFF_U1) * 4;
            for (int i = tid; i < n16; i += TPB) cp16(dst + i * 16, gsrc + i * 16);
            CP_COMMIT();
            CP_WAIT(1);
        } else {
            CP_WAIT(0);
        }
        __syncthreads();   // current u tile visible

        // ================= layer 1: pre-h = u_even @ W1 =================
        #pragma unroll
        for (int mt = 0; mt < 2; mt++)
            #pragma unroll
            for (int nt = 0; nt < 4; nt++)
                #pragma unroll
                for (int f = 0; f < 4; f++) acc[mt][nt][f] = 0.0f;

        #pragma unroll
        for (int kc = 0; kc < 3; kc++) {
            const int kb = kc * 8;
            const int k0 = kb + t4, k1 = k0 + 4;
            const bool q0 = k0 < 18, q1 = k1 < 18;
            uint32_t A[2][4];
            #pragma unroll
            for (int mt = 0; mt < 2; mt++) {
                int r = wm + mt * 16 + gid;
                A[mt][0] = q0 ? uU[r * 36 + 2 * k0]       : 0u;
                A[mt][1] = q0 ? uU[(r + 8) * 36 + 2 * k0] : 0u;
                A[mt][2] = q1 ? uU[r * 36 + 2 * k1]       : 0u;
                A[mt][3] = q1 ? uU[(r + 8) * 36 + 2 * k1] : 0u;
            }
            #pragma unroll
            for (int nt = 0; nt < 4; nt++) {
                int c = wn + nt * 8 + gid;
                uint32_t b0  = smu[OFF_W1 + k0 * LDH + c];
                uint32_t b1f = smu[OFF_W1 + k1 * LDH + c];
                #pragma unroll
                for (int mt = 0; mt < 2; mt++)
                    mma_tf32(acc[mt][nt], A[mt][0], A[mt][1], A[mt][2], A[mt][3], b0, b1f);
            }
        }

        // bias + fast tanh, stage h (raw f32 bits; HMMA truncates to tf32)
        #pragma unroll
        for (int mt = 0; mt < 2; mt++) {
            #pragma unroll
            for (int nt = 0; nt < 4; nt++) {
                int c = wn + nt * 8 + 2 * t4;
                float bb0 = sm[OFF_B1 + c], bb1 = sm[OFF_B1 + c + 1];
                int r0 = wm + mt * 16 + gid;
                float h00 = tanh_fast(acc[mt][nt][0] + bb0);
                float h01 = tanh_fast(acc[mt][nt][1] + bb1);
                float h10 = tanh_fast(acc[mt][nt][2] + bb0);
                float h11 = tanh_fast(acc[mt][nt][3] + bb1);
                *(float2*)&sm[OFF_H + r0 * LDH + c]       = make_float2(h00, h01);
                *(float2*)&sm[OFF_H + (r0 + 8) * LDH + c] = make_float2(h10, h11);
            }
        }
        __syncthreads();

        // ================= layer 2: D = H @ W2 =================
        #pragma unroll
        for (int mt = 0; mt < 2; mt++)
            #pragma unroll
            for (int nt = 0; nt < 4; nt++)
                #pragma unroll
                for (int f = 0; f < 4; f++) acc[mt][nt][f] = 0.0f;

        #pragma unroll
        for (int kc = 0; kc < 16; kc++) {
            const int kb = kc * 8;
            uint32_t A[2][4];
            #pragma unroll
            for (int mt = 0; mt < 2; mt++) {
                int r = wm + mt * 16 + gid;
                A[mt][0] = smu[OFF_H + r * LDH + kb + t4];
                A[mt][1] = smu[OFF_H + (r + 8) * LDH + kb + t4];
                A[mt][2] = smu[OFF_H + r * LDH + kb + t4 + 4];
                A[mt][3] = smu[OFF_H + (r + 8) * LDH + kb + t4 + 4];
            }
            #pragma unroll
            for (int nt = 0; nt < 4; nt++) {
                int c = wn + nt * 8 + gid;
                uint32_t b0  = smu[OFF_W2 + (kb + t4) * LDH + c];
                uint32_t b1f = smu[OFF_W2 + (kb + t4 + 4) * LDH + c];
                #pragma unroll
                for (int mt = 0; mt < 2; mt++)
                    mma_tf32(acc[mt][nt], A[mt][0], A[mt][1], A[mt][2], A[mt][3], b0, b1f);
            }
        }
        __syncthreads();   // all H reads done before overwriting with D

        #pragma unroll
        for (int mt = 0; mt < 2; mt++) {
            #pragma unroll
            for (int nt = 0; nt < 4; nt++) {
                int c = wn + nt * 8 + 2 * t4;
                int r0 = wm + mt * 16 + gid;
                *(float2*)&sm[OFF_H + r0 * LDH + c]       = make_float2(acc[mt][nt][0], acc[mt][nt][1]);
                *(float2*)&sm[OFF_H + (r0 + 8) * LDH + c] = make_float2(acc[mt][nt][2], acc[mt][nt][3]);
            }
        }
        __syncthreads();

        // ================= fused epilogue (division-free) =================
        const int rowbase = tile * TRR;
        int grow = rowbase + erow;
        if (grow < N) {
            const float* ur = &sU[erow * 36];
            const float* hr = &sm[OFF_H + erow * LDH];
            float* gout = &out[(size_t)grow * 36];
            #pragma unroll
            for (int j = 0; j < 5; j++) {
                int i = esub + 4 * j;
                if (i < 18) {
                    int i2 = 2 * i;
                    float uE  = ur[i2];
                    float uB  = ur[i2 + 1];
                    float uA  = ur[(i2 + 35) % 36];
                    float uC  = ur[(i2 + 3) % 36];
                    float um2 = ur[(i2 + 34) % 36];
                    float up2 = ur[(i2 + 2) % 36];

                    float e = r10 + r11 * uE + r12 * uB
                            + r13 * (um2 * uA) + r14 * (uA * up2) + r15 * (uE * uB);
                    float o = r20 + r21 * uB + r22 * (uA * uE) + r23 * (uE * up2);

                    float a0 = hr[3 * i]     + sm[OFF_B2A + 3 * i];
                    float a1 = hr[3 * i + 1] + sm[OFF_B2A + 3 * i + 1];
                    float a2 = hr[3 * i + 2] + sm[OFF_B2A + 3 * i + 2];
                    float d0 = hr[54 + 4 * i]     + sm[OFF_B2B + 4 * i];
                    float d1 = hr[54 + 4 * i + 1] + sm[OFF_B2B + 4 * i + 1];
                    float d2 = hr[54 + 4 * i + 2] + sm[OFF_B2B + 4 * i + 2];
                    float d3 = hr[54 + 4 * i + 3] + sm[OFF_B2B + 4 * i + 3];

                    float oE = a0 + a1 * uA + a2 * uB + e;
                    float oO = d0 + d1 * uA + d2 * uB + d3 * uC + o;
                    *(float2*)&gout[i2] = make_float2(oE, oO);
                }
            }
        }
    }
}

extern "C" void kernel_launch(void* const* d_in, const int* in_sizes, int n_in,
                              void* d_out, int out_size)
{
    // inputs: 0=t 1=u 2=reg1 3=reg2 4=W1 5=b1 6=W2a 7=b2a 8=W2b 9=b2b
    const float* u    = (const float*)d_in[1];
    const float* reg1 = (const float*)d_in[2];
    const float* reg2 = (const float*)d_in[3];
    const float* W1   = (const float*)d_in[4];
    const float* b1   = (const float*)d_in[5];
    const float* W2a  = (const float*)d_in[6];
    const float* b2a  = (const float*)d_in[7];
    const float* W2b  = (const float*)d_in[8];
    const float* b2b  = (const float*)d_in[9];
    float* out = (float*)d_out;

    int N = in_sizes[1] / 36;
    int ntiles = (N + TRR - 1) / TRR;
    int smem_bytes = SMEM_FLOATS * (int)sizeof(float);

    int nsm = 148;
    cudaDeviceGetAttribute(&nsm, cudaDevAttrMultiProcessorCount, 0);
    int grid = nsm < ntiles ? nsm : ntiles;

    cudaFuncSetAttribute(mix_mma_pers,
                         cudaFuncAttributeMaxDynamicSharedMemorySize, smem_bytes);
    mix_mma_pers<<<grid, TPB, smem_bytes>>>(
        u, reg1, reg2, W1, b1, W2a, b2a, W2b, b2b, out, N, ntiles);
}

// round 5
// speedup vs baseline: 3.9855x; 1.1121x over previous
#include <cuda_runtime.h>
#include <cstdint>
#include <math.h>

#define TPB 256
#define TRR 128
#define LDH 132   // H row stride: A-frag banks (4*gid+t4) conflict-free
#define LDW 136   // W1/W2 row stride: B-frag banks (8*t4+gid) conflict-free

// ---- shared memory layout (float offsets) ----
#define OFF_W2   0                     // 128*136 [k][n] tf32 bits
#define OFF_H    (OFF_W2 + 128*LDW)    // 128*132 [m][k] h bits, then D (f32)
#define OFF_W1   (OFF_H + 128*LDH)     // 24*136  [k][n] tf32 bits (k>=18 zero)
#define OFF_U0   (OFF_W1 + 24*LDW)     // 128*36 raw u, buffer 0
#define OFF_U1   (OFF_U0 + TRR*36)     // buffer 1
#define OFF_B1   (OFF_U1 + TRR*36)     // 128
#define OFF_B2A  (OFF_B1 + 128)        // 54 -> pad 56
#define OFF_B2B  (OFF_B2A + 56)        // 72
#define OFF_R    (OFF_B2B + 72)        // 10
#define SMEM_FLOATS (OFF_R + 12)

__device__ __forceinline__ uint32_t f2tf32(float x) {
    uint32_t r;
    asm("cvt.rna.tf32.f32 %0, %1;" : "=r"(r) : "f"(x));
    return r;
}
__device__ __forceinline__ float tanh_fast(float x) {
    float y;
    asm("tanh.approx.f32 %0, %1;" : "=f"(y) : "f"(x));
    return y;
}
__device__ __forceinline__ void mma_tf32(float c[4],
                                         uint32_t a0, uint32_t a1, uint32_t a2, uint32_t a3,
                                         uint32_t b0, uint32_t b1) {
    asm volatile(
        "mma.sync.aligned.m16n8k8.row.col.f32.tf32.tf32.f32 "
        "{%0,%1,%2,%3}, {%4,%5,%6,%7}, {%8,%9}, {%0,%1,%2,%3};"
        : "+f"(c[0]), "+f"(c[1]), "+f"(c[2]), "+f"(c[3])
        : "r"(a0), "r"(a1), "r"(a2), "r"(a3), "r"(b0), "r"(b1));
}
__device__ __forceinline__ void cp16(uint32_t dst, const void* src) {
    asm volatile("cp.async.cg.shared.global [%0], [%1], 16;" :: "r"(dst), "l"(src));
}
#define CP_COMMIT() asm volatile("cp.async.commit_group;" ::: "memory")
#define CP_WAIT(n)  asm volatile("cp.async.wait_group %0;" :: "n"(n) : "memory")

__global__ __launch_bounds__(TPB, 1)
void mix_mma_v5(const float* __restrict__ u,
                const float* __restrict__ reg1,
                const float* __restrict__ reg2,
                const float* __restrict__ W1,
                const float* __restrict__ b1,
                const float* __restrict__ W2a,
                const float* __restrict__ b2a,
                const float* __restrict__ W2b,
                const float* __restrict__ b2b,
                float* __restrict__ out,
                int N, int ntiles)
{
    extern __shared__ float sm[];
    uint32_t* smu = (uint32_t*)sm;
    const uint32_t smem_base = (uint32_t)__cvta_generic_to_shared(sm);

    const int tid  = threadIdx.x;
    const int wid  = tid >> 5;
    const int lane = tid & 31;
    const int gid  = lane >> 2;        // 0..7
    const int t4   = lane & 3;         // 0..3
    const int wm   = (wid & 1) * 64;   // 2 m-groups, 64 rows each
    const int wn   = (wid >> 1) * 32;  // 4 n-groups, 32 cols each

    // ---- prologue: prefetch first u tile into buffer 0 ----
    const int tile0 = blockIdx.x;
    {
        int rows = min(TRR, N - tile0 * TRR);
        int n16  = rows * 9;
        const char* gsrc = (const char*)(u + (size_t)tile0 * TRR * 36);
        uint32_t dst = smem_base + OFF_U0 * 4;
        for (int i = tid; i < n16; i += TPB) cp16(dst + i * 16, gsrc + i * 16);
    }
    CP_COMMIT();

    // ---- stage weights once (tf32-rounded), biases, reg coeffs ----
    for (int i = tid; i < 128 * 128; i += TPB) {
        int k = i >> 7, n = i & 127;
        float v = 0.0f;
        if (n < 54)       v = W2a[k * 54 + n];
        else if (n < 126) v = W2b[k * 72 + (n - 54)];
        smu[OFF_W2 + k * LDW + n] = f2tf32(v);
    }
    for (int i = tid; i < 24 * 128; i += TPB) {
        int k = i >> 7, n = i & 127;
        float v = (k < 18) ? W1[k * 128 + n] : 0.0f;
        smu[OFF_W1 + k * LDW + n] = f2tf32(v);
    }
    if (tid < 128) sm[OFF_B1 + tid]  = b1[tid];
    if (tid < 54)  sm[OFF_B2A + tid] = b2a[tid];
    if (tid < 72)  sm[OFF_B2B + tid] = b2b[tid];
    if (tid < 6)   sm[OFF_R + tid]     = reg1[tid];
    if (tid < 4)   sm[OFF_R + 6 + tid] = reg2[tid];
    __syncthreads();

    // ---- cache invariant B fragments in registers ----
    uint32_t Bc1[3][4][2];           // layer-1 W1 frags (all 3 k-chunks)
    uint32_t Bc2[8][4][2];           // layer-2 W2 frags, k-chunks 0..7
    #pragma unroll
    for (int kc = 0; kc < 3; kc++) {
        int k0 = kc * 8 + t4;
        #pragma unroll
        for (int nt = 0; nt < 4; nt++) {
            int c = wn + nt * 8 + gid;
            Bc1[kc][nt][0] = smu[OFF_W1 + k0 * LDW + c];
            Bc1[kc][nt][1] = smu[OFF_W1 + (k0 + 4) * LDW + c];
        }
    }
    #pragma unroll
    for (int kc = 0; kc < 8; kc++) {
        int k0 = kc * 8 + t4;
        #pragma unroll
        for (int nt = 0; nt < 4; nt++) {
            int c = wn + nt * 8 + gid;
            Bc2[kc][nt][0] = smu[OFF_W2 + k0 * LDW + c];
            Bc2[kc][nt][1] = smu[OFF_W2 + (k0 + 4) * LDW + c];
        }
    }

    const float r10 = sm[OFF_R + 0], r11 = sm[OFF_R + 1], r12 = sm[OFF_R + 2];
    const float r13 = sm[OFF_R + 3], r14 = sm[OFF_R + 4], r15 = sm[OFF_R + 5];
    const float r20 = sm[OFF_R + 6], r21 = sm[OFF_R + 7], r22 = sm[OFF_R + 8], r23 = sm[OFF_R + 9];

    float acc[4][4][4];   // [mt][nt][frag]

    int it = 0;
    for (int tile = tile0; tile < ntiles; tile += gridDim.x, ++it) {
        const int b = it & 1;
        const float* sU = sm + (b ? OFF_U1 : OFF_U0);
        const uint32_t* uU = (const uint32_t*)sU;

        __syncthreads();   // prior epilogue done -> other buffer reusable
        int ntile = tile + gridDim.x;
        if (ntile < ntiles) {
            int rows = min(TRR, N - ntile * TRR);
            int n16  = rows * 9;
            const char* gsrc = (const char*)(u + (size_t)ntile * TRR * 36);
            uint32_t dst = smem_base + (b ? OFF_U0 : OFF_U1) * 4;
            for (int i = tid; i < n16; i += TPB) cp16(dst + i * 16, gsrc + i * 16);
            CP_COMMIT();
            CP_WAIT(1);
        } else {
            CP_WAIT(0);
        }
        __syncthreads();   // current u tile visible

        // ================= layer 1: pre-h = u_even @ W1 =================
        #pragma unroll
        for (int mt = 0; mt < 4; mt++)
            #pragma unroll
            for (int nt = 0; nt < 4; nt++)
                #pragma unroll
                for (int f = 0; f < 4; f++) acc[mt][nt][f] = 0.0f;

        #pragma unroll
        for (int kc = 0; kc < 3; kc++) {
            const int k0 = kc * 8 + t4, k1 = k0 + 4;
            const bool q0 = k0 < 18, q1 = k1 < 18;
            uint32_t A[4][4];
            #pragma unroll
            for (int mt = 0; mt < 4; mt++) {
                int r = wm + mt * 16 + gid;
                A[mt][0] = q0 ? uU[r * 36 + 2 * k0]       : 0u;
                A[mt][1] = q0 ? uU[(r + 8) * 36 + 2 * k0] : 0u;
                A[mt][2] = q1 ? uU[r * 36 + 2 * k1]       : 0u;
                A[mt][3] = q1 ? uU[(r + 8) * 36 + 2 * k1] : 0u;
            }
            #pragma unroll
            for (int nt = 0; nt < 4; nt++)
                #pragma unroll
                for (int mt = 0; mt < 4; mt++)
                    mma_tf32(acc[mt][nt], A[mt][0], A[mt][1], A[mt][2], A[mt][3],
                             Bc1[kc][nt][0], Bc1[kc][nt][1]);
        }

        // bias + fast tanh, stage h
        #pragma unroll
        for (int mt = 0; mt < 4; mt++) {
            #pragma unroll
            for (int nt = 0; nt < 4; nt++) {
                int c = wn + nt * 8 + 2 * t4;
                float bb0 = sm[OFF_B1 + c], bb1 = sm[OFF_B1 + c + 1];
                int r0 = wm + mt * 16 + gid;
                float h00 = tanh_fast(acc[mt][nt][0] + bb0);
                float h01 = tanh_fast(acc[mt][nt][1] + bb1);
                float h10 = tanh_fast(acc[mt][nt][2] + bb0);
                float h11 = tanh_fast(acc[mt][nt][3] + bb1);
                *(float2*)&sm[OFF_H + r0 * LDH + c]       = make_float2(h00, h01);
                *(float2*)&sm[OFF_H + (r0 + 8) * LDH + c] = make_float2(h10, h11);
            }
        }
        __syncthreads();

        // ================= layer 2: D = H @ W2 =================
        #pragma unroll
        for (int mt = 0; mt < 4; mt++)
            #pragma unroll
            for (int nt = 0; nt < 4; nt++)
                #pragma unroll
                for (int f = 0; f < 4; f++) acc[mt][nt][f] = 0.0f;

        #pragma unroll
        for (int kc = 0; kc < 16; kc++) {
            const int kb = kc * 8;
            uint32_t A[4][4];
            #pragma unroll
            for (int mt = 0; mt < 4; mt++) {
                int r = wm + mt * 16 + gid;
                A[mt][0] = smu[OFF_H + r * LDH + kb + t4];
                A[mt][1] = smu[OFF_H + (r + 8) * LDH + kb + t4];
                A[mt][2] = smu[OFF_H + r * LDH + kb + t4 + 4];
                A[mt][3] = smu[OFF_H + (r + 8) * LDH + kb + t4 + 4];
            }
            if (kc < 8) {
                #pragma unroll
                for (int nt = 0; nt < 4; nt++)
                    #pragma unroll
                    for (int mt = 0; mt < 4; mt++)
                        mma_tf32(acc[mt][nt], A[mt][0], A[mt][1], A[mt][2], A[mt][3],
                                 Bc2[kc][nt][0], Bc2[kc][nt][1]);
            } else {
                #pragma unroll
                for (int nt = 0; nt < 4; nt++) {
                    int c = wn + nt * 8 + gid;
                    uint32_t b0  = smu[OFF_W2 + (kb + t4) * LDW + c];
                    uint32_t b1f = smu[OFF_W2 + (kb + t4 + 4) * LDW + c];
                    #pragma unroll
                    for (int mt = 0; mt < 4; mt++)
                        mma_tf32(acc[mt][nt], A[mt][0], A[mt][1], A[mt][2], A[mt][3], b0, b1f);
                }
            }
        }
        __syncthreads();   // all H reads done before overwriting with D

        #pragma unroll
        for (int mt = 0; mt < 4; mt++) {
            #pragma unroll
            for (int nt = 0; nt < 4; nt++) {
                int c = wn + nt * 8 + 2 * t4;
                int r0 = wm + mt * 16 + gid;
                *(float2*)&sm[OFF_H + r0 * LDH + c]       = make_float2(acc[mt][nt][0], acc[mt][nt][1]);
                *(float2*)&sm[OFF_H + (r0 + 8) * LDH + c] = make_float2(acc[mt][nt][2], acc[mt][nt][3]);
            }
        }
        __syncthreads();

        // ================= fused epilogue =================
        const int rowbase = tile * TRR;
        #pragma unroll
        for (int half = 0; half < 2; half++) {
            int erow = half * 64 + (tid >> 2);
            int esub = tid & 3;
            int grow = rowbase + erow;
            if (grow < N) {
                const float* ur = &sU[erow * 36];
                const float* hr = &sm[OFF_H + erow * LDH];
                float* gout = &out[(size_t)grow * 36];
                #pragma unroll
                for (int j = 0; j < 5; j++) {
                    int i = esub + 4 * j;
                    if (i < 18) {
                        int i2 = 2 * i;
                        float uE  = ur[i2];
                        float uB  = ur[i2 + 1];
                        float uA  = ur[(i2 + 35) % 36];
                        float uC  = ur[(i2 + 3) % 36];
                        float um2 = ur[(i2 + 34) % 36];
                        float up2 = ur[(i2 + 2) % 36];

                        float e = r10 + r11 * uE + r12 * uB
                                + r13 * (um2 * uA) + r14 * (uA * up2) + r15 * (uE * uB);
                        float o = r20 + r21 * uB + r22 * (uA * uE) + r23 * (uE * up2);

                        float a0 = hr[3 * i]     + sm[OFF_B2A + 3 * i];
                        float a1 = hr[3 * i + 1] + sm[OFF_B2A + 3 * i + 1];
                        float a2 = hr[3 * i + 2] + sm[OFF_B2A + 3 * i + 2];
                        float d0 = hr[54 + 4 * i]     + sm[OFF_B2B + 4 * i];
                        float d1 = hr[54 + 4 * i + 1] + sm[OFF_B2B + 4 * i + 1];
                        float d2 = hr[54 + 4 * i + 2] + sm[OFF_B2B + 4 * i + 2];
                        float d3 = hr[54 + 4 * i + 3] + sm[OFF_B2B + 4 * i + 3];

                        float oE = a0 + a1 * uA + a2 * uB + e;
                        float oO = d0 + d1 * uA + d2 * uB + d3 * uC + o;
                        *(float2*)&gout[i2] = make_float2(oE, oO);
                    }
                }
            }
        }
    }
}

extern "C" void kernel_launch(void* const* d_in, const int* in_sizes, int n_in,
                              void* d_out, int out_size)
{
    // inputs: 0=t 1=u 2=reg1 3=reg2 4=W1 5=b1 6=W2a 7=b2a 8=W2b 9=b2b
    const float* u    = (const float*)d_in[1];
    const float* reg1 = (const float*)d_in[2];
    const float* reg2 = (const float*)d_in[3];
    const float* W1   = (const float*)d_in[4];
    const float* b1   = (const float*)d_in[5];
    const float* W2a  = (const float*)d_in[6];
    const float* b2a  = (const float*)d_in[7];
    const float* W2b  = (const float*)d_in[8];
    const float* b2b  = (const float*)d_in[9];
    float* out = (float*)d_out;

    int N = in_sizes[1] / 36;
    int ntiles = (N + TRR - 1) / TRR;
    int smem_bytes = SMEM_FLOATS * (int)sizeof(float);

    int nsm = 148;
    cudaDeviceGetAttribute(&nsm, cudaDevAttrMultiProcessorCount, 0);
    int grid = nsm < ntiles ? nsm : ntiles;

    cudaFuncSetAttribute(mix_mma_v5,
                         cudaFuncAttributeMaxDynamicSharedMemorySize, smem_bytes);
    mix_mma_v5<<<grid, TPB, smem_bytes>>>(
        u, reg1, reg2, W1, b1, W2a, b2a, W2b, b2b, out, N, ntiles);
}